// round 14
// baseline (speedup 1.0000x reference)
#include <cuda_runtime.h>
#include <cuda_fp16.h>
#include <cstdint>
#include <cstddef>

#define NUM_NODES 100000
#define FEAT_DIM  256
#define BATCH     4096
#define F1N       25
#define F2N       10

// ---------------- static scratch ----------------
__device__ __half g_Ph[(size_t)NUM_NODES * 256];    // P = emb @ W1[:, :256].T
__device__ __half g_Qh[(size_t)NUM_NODES * 256];    // Q = emb @ W1[:, 256:].T
__device__ __half g_B1h[256 * 512];                 // [K=256][N=512] fp16
__device__ __half g_W2th[512 * 256];                // W2^T fp16 [k][n]
__device__ float  g_W3t[256 * 64];                  // W3^T fp32
__device__ __half g_combh[(size_t)BATCH * 512];     // [h0 | h1] fp16
__device__ float  g_E[(size_t)BATCH * 256];

// pack two fp32 -> fp16x2 (x -> lower, y -> upper; same rounding as __floats2half2_rn)
__device__ __forceinline__ uint32_t pack_h2(float x, float y) {
    uint32_t r;
    asm("cvt.rn.f16x2.f32 %0, %1, %2;" : "=r"(r) : "f"(y), "f"(x));
    return r;
}

// ---------------- weight prep only (emb conversion now fused into PQ GEMM) ----
__global__ void prep_w(const float* __restrict__ W1,
                       const float* __restrict__ W2,
                       const float* __restrict__ W3) {
    int idx = blockIdx.x * blockDim.x + threadIdx.x;
    if (idx < 256 * 512) {   // B1h[k][n]
        int k = idx >> 9, n = idx & 511;
        float v = (n < 256) ? W1[n * 512 + k] : W1[(n - 256) * 512 + 256 + k];
        g_B1h[idx] = __float2half(v);
    }
    if (idx < 512 * 256) {   // W2th[k][n] = W2[n][k]
        int k = idx >> 8, n = idx & 255;
        g_W2th[idx] = __float2half(W2[n * 512 + k]);
    }
    if (idx < 256 * 64) {    // W3t[k][n] = W3[n][k]
        int k = idx >> 6, n = idx & 63;
        g_W3t[idx] = W3[n * 256 + k];
    }
}

// ---------------- fp16 tensor-core GEMM, BK=64, NSTAGE cp.async ----------------
// CONVA=true (requires MT=2, NSTAGE=2): A is fp32; tiles are LDG'd, converted to
// fp16 in-register, and STS'd into the next stage's A buffer, interleaved with
// the kk MMA loop. CONVA=false: A is fp16 via cp.async (unchanged R13 path).

__device__ __forceinline__ uint32_t smem_u32(const void* p) {
    return (uint32_t)__cvta_generic_to_shared(p);
}
__device__ __forceinline__ uint32_t a2_off(int row, int c) {
    return (uint32_t)(row * 128 + ((c ^ (row & 7)) * 16));
}
__device__ __forceinline__ uint32_t b2_off(int k, int c) {
    return (uint32_t)(k * 256 + (((c & 8) | ((c ^ k) & 7)) * 16));
}
__device__ __forceinline__ void cp16(uint32_t dst, const void* src, int pred16) {
    asm volatile("cp.async.cg.shared.global [%0], [%1], 16, %2;"
                 :: "r"(dst), "l"(src), "r"(pred16));
}
__device__ __forceinline__ void ldsm4(uint32_t& r0, uint32_t& r1, uint32_t& r2,
                                      uint32_t& r3, uint32_t a) {
    asm volatile("ldmatrix.sync.aligned.m8n8.x4.shared.b16 {%0,%1,%2,%3}, [%4];"
                 : "=r"(r0), "=r"(r1), "=r"(r2), "=r"(r3) : "r"(a));
}
__device__ __forceinline__ void ldsm4t(uint32_t& r0, uint32_t& r1, uint32_t& r2,
                                       uint32_t& r3, uint32_t a) {
    asm volatile("ldmatrix.sync.aligned.m8n8.x4.trans.shared.b16 {%0,%1,%2,%3}, [%4];"
                 : "=r"(r0), "=r"(r1), "=r"(r2), "=r"(r3) : "r"(a));
}
__device__ __forceinline__ void mma16816(float* d, const uint32_t* a, uint32_t b0,
                                         uint32_t b1) {
    asm volatile(
        "mma.sync.aligned.m16n8k16.row.col.f32.f16.f16.f32 "
        "{%0,%1,%2,%3}, {%4,%5,%6,%7}, {%8,%9}, {%0,%1,%2,%3};\n"
        : "+f"(d[0]), "+f"(d[1]), "+f"(d[2]), "+f"(d[3])
        : "r"(a[0]), "r"(a[1]), "r"(a[2]), "r"(a[3]), "r"(b0), "r"(b1));
}
__device__ __forceinline__ void store2o(float* C, size_t off, float x, float y) {
    *reinterpret_cast<float2*>(C + off) = make_float2(x, y);
}
__device__ __forceinline__ void store2o(__half* C, size_t off, float x, float y) {
    *reinterpret_cast<__half2*>(C + off) = __floats2half2_rn(x, y);
}

template <bool RELU, int MT, typename OutT, bool SPLIT, int NSTAGE, bool CONVA>
__global__ __launch_bounds__(256, 2)
void gemm_f16(const void* __restrict__ Ap, const __half* __restrict__ B,
              OutT* __restrict__ C0, OutT* __restrict__ C1, int M, int N, int K) {
    const int BM  = MT * 64;
    const int ASZ = BM * 128;
    const int BSZ = 64 * 256;
    const int STG = ASZ + BSZ;
    extern __shared__ __align__(16) char smem[];

    const __half* Ah = reinterpret_cast<const __half*>(Ap);
    const float*  Af = reinterpret_cast<const float*>(Ap);

    const int tid  = threadIdx.x;
    const int lane = tid & 31;
    const int wid  = tid >> 5;
    const int warpM = wid & 3;
    const int warpN = wid >> 2;
    const int wbase = warpM * MT * 16;
    const int j8 = lane & 7;
    const int g8 = lane >> 3;
    const int m0 = blockIdx.y * BM;
    const int n0 = blockIdx.x * 128;
    const uint32_t sbase = smem_u32(smem);

    float acc[MT][8][4];
#pragma unroll
    for (int mt = 0; mt < MT; mt++)
#pragma unroll
        for (int nt = 0; nt < 8; nt++)
#pragma unroll
            for (int c = 0; c < 4; c++) acc[mt][nt][c] = 0.f;

    const int NK = K / 64;

    // CONVA thread->tile mapping (MT=2 only): row = tid>>1 (0..127), half = tid&1;
    // thread owns fp32 cols [half*32, half*32+32) of its row per stage = 4 pairs
    // of float4; pair p -> fp16 16B chunk (half*4 + p).
    const int ar = tid >> 1;
    const int ah = tid & 1;
    const int agm = m0 + ar;
    const bool aok = CONVA && (agm < M);

    auto lda_pair = [&](int s, int p, float4& v0, float4& v1) {
        if (aok) {
            const float* src = Af + (size_t)agm * K + s * 64 + ah * 32 + p * 8;
            v0 = *reinterpret_cast<const float4*>(src);
            v1 = *reinterpret_cast<const float4*>(src + 4);
        } else {
            v0 = make_float4(0.f, 0.f, 0.f, 0.f);
            v1 = make_float4(0.f, 0.f, 0.f, 0.f);
        }
    };
    auto sta_pair = [&](int s, int p, const float4& v0, const float4& v1) {
        uint4 o = make_uint4(pack_h2(v0.x, v0.y), pack_h2(v0.z, v0.w),
                             pack_h2(v1.x, v1.y), pack_h2(v1.z, v1.w));
        *reinterpret_cast<uint4*>(smem + (s % 2) * STG + a2_off(ar, ah * 4 + p)) = o;
    };

    // issue one 64-wide K stage of B (and, when !CONVA, A) via cp.async
    auto issue = [&](int s) {
        const uint32_t as = sbase + (s % NSTAGE) * STG;
        const uint32_t bs = as + ASZ;
        const int kb = s * 64;
        if (!CONVA) {
#pragma unroll
            for (int it = 0; it < MT * 2; it++) {
                int i = tid + it * 256;
                int row = i >> 3, c = i & 7;
                int gm = m0 + row;
                cp16(as + a2_off(row, c), Ah + (size_t)gm * K + kb + c * 8,
                     (gm < M) ? 16 : 0);
            }
        }
#pragma unroll
        for (int it = 0; it < 4; it++) {
            int i = tid + it * 256;
            int k = i >> 4, c = i & 15;
            cp16(bs + b2_off(k, c), B + (size_t)(kb + k) * N + n0 + c * 8, 16);
        }
        asm volatile("cp.async.commit_group;");
    };

    if (NSTAGE == 2) {
        issue(0);
    } else {
        issue(0);
        if (NK > 1) issue(1);
    }
    if (CONVA) {
        // prologue: fill A stage 0 (LDG + cvt + STS)
#pragma unroll
        for (int p = 0; p < 4; p++) {
            float4 v0, v1;
            lda_pair(0, p, v0, v1);
            sta_pair(0, p, v0, v1);
        }
    }

    for (int i = 0; i < NK; i++) {
        if (NSTAGE == 2) {
            if (i + 1 < NK) {
                issue(i + 1);
                asm volatile("cp.async.wait_group 1;");
            } else {
                asm volatile("cp.async.wait_group 0;");
            }
            __syncthreads();
        } else {
            if (i == NK - 1) asm volatile("cp.async.wait_group 0;");
            else             asm volatile("cp.async.wait_group 1;");
            __syncthreads();
            if (i + 2 < NK) issue(i + 2);
        }

        const uint32_t as = sbase + (i % NSTAGE) * STG;
        const uint32_t bs = as + ASZ;

        const bool doA = CONVA && (i + 1 < NK);
        float4 la0, la1;
        if (doA) lda_pair(i + 1, 0, la0, la1);   // pair 0 in flight

#pragma unroll
        for (int kk = 0; kk < 4; kk++) {
            float4 lb0, lb1;
            if (doA && kk < 3) lda_pair(i + 1, kk + 1, lb0, lb1);

            uint32_t afr[MT][4];
#pragma unroll
            for (int mt = 0; mt < MT; mt++) {
                int row = wbase + mt * 16 + (g8 & 1) * 8 + j8;
                int ch  = kk * 2 + (g8 >> 1);
                ldsm4(afr[mt][0], afr[mt][1], afr[mt][2], afr[mt][3],
                      as + a2_off(row, ch));
            }
#pragma unroll
            for (int nt2 = 0; nt2 < 4; nt2++) {
                int kb = kk * 16 + (g8 & 1) * 8 + j8;
                int cb = ((warpN * 64 + nt2 * 16) >> 3) + (g8 >> 1);
                uint32_t b0, b1, b2, b3;
                ldsm4t(b0, b1, b2, b3, bs + b2_off(kb, cb));
#pragma unroll
                for (int mt = 0; mt < MT; mt++) {
                    mma16816(acc[mt][nt2 * 2 + 0], afr[mt], b0, b1);
                    mma16816(acc[mt][nt2 * 2 + 1], afr[mt], b2, b3);
                }
            }

            if (doA) {
                sta_pair(i + 1, kk, la0, la1);   // store pair kk (loaded last kk)
                la0 = lb0; la1 = lb1;
            }
        }
        __syncthreads();
    }

    const int gid = lane >> 2, lg = lane & 3;
    OutT* Cp = C0;
    int nbase = n0, Nout = N;
    if (SPLIT) {
        Nout = 256;
        if (n0 >= 256) { Cp = C1; nbase = n0 - 256; }
    }
#pragma unroll
    for (int mt = 0; mt < MT; mt++) {
        int r0 = m0 + wbase + mt * 16 + gid;
#pragma unroll
        for (int half = 0; half < 2; half++) {
            int gm = r0 + half * 8;
            if (gm >= M) continue;
#pragma unroll
            for (int nt = 0; nt < 8; nt++) {
                float x = acc[mt][nt][half * 2 + 0];
                float y = acc[mt][nt][half * 2 + 1];
                if (RELU) { x = fmaxf(x, 0.f); y = fmaxf(y, 0.f); }
                int col = nbase + warpN * 64 + nt * 8 + lg * 2;
                store2o(Cp, (size_t)gm * Nout + col, x, y);
            }
        }
    }
}

#define SMEM_PQ (2 * (128 * 128 + 64 * 256))   // 65536 B  (MT=2, 2-stage)
#define SMEM_W2 (3 * (64 * 128 + 64 * 256))    // 73728 B  (MT=1, 3-stage)

// ---------------- fused gather / mean / relu (R13, unchanged) ----------------
__global__ __launch_bounds__(128)
void gather_fuse(const int* __restrict__ T0, const int* __restrict__ T1,
                 const int* __restrict__ T2) {
    const int b = blockIdx.x;
    const int tid = threadIdx.x;
    const int lane = tid & 31;
    const int w = tid >> 5;

    __shared__ __align__(16) float sH[4 * 256];
    __shared__ __align__(16) float sQ[4 * 256];
    __shared__ int sT1[F1N];
    __shared__ int sT2[F1N * F2N];

    if (tid < F1N) sT1[tid] = T1[b * F1N + tid];
    for (int i = tid; i < F1N * F2N; i += 128) sT2[i] = T2[b * F1N * F2N + i];
    __syncthreads();

    const uint4* __restrict__ Pv = reinterpret_cast<const uint4*>(g_Ph);
    const uint4* __restrict__ Qv = reinterpret_cast<const uint4*>(g_Qh);

    float hacc[8], qacc[8];
#pragma unroll
    for (int c = 0; c < 8; c++) { hacc[c] = 0.f; qacc[c] = 0.f; }

    for (int i = w; i < F1N; i += 4) {
        const int n1 = sT1[i];
        uint4 pr = Pv[(size_t)n1 * 32 + lane];
        uint4 qr = Qv[(size_t)n1 * 32 + lane];
        uint4 aj[F2N];
#pragma unroll
        for (int j = 0; j < F2N; j++)
            aj[j] = Qv[(size_t)sT2[i * F2N + j] * 32 + lane];

        __half2 s[4];
#pragma unroll
        for (int c = 0; c < 4; c++) {
            __half2 t01 = __hadd2(((const __half2*)&aj[0])[c], ((const __half2*)&aj[1])[c]);
            __half2 t23 = __hadd2(((const __half2*)&aj[2])[c], ((const __half2*)&aj[3])[c]);
            __half2 t45 = __hadd2(((const __half2*)&aj[4])[c], ((const __half2*)&aj[5])[c]);
            __half2 t67 = __hadd2(((const __half2*)&aj[6])[c], ((const __half2*)&aj[7])[c]);
            __half2 t89 = __hadd2(((const __half2*)&aj[8])[c], ((const __half2*)&aj[9])[c]);
            __half2 q0 = __hadd2(t01, t23);
            __half2 q1 = __hadd2(t45, t67);
            s[c] = __hadd2(__hadd2(q0, q1), t89);
        }

#pragma unroll
        for (int c = 0; c < 4; c++) {
            float2 sf = __half22float2(s[c]);
            float2 pf = __half22float2(((const __half2*)&pr)[c]);
            float2 qf = __half22float2(((const __half2*)&qr)[c]);
            qacc[2 * c + 0] += qf.x;
            qacc[2 * c + 1] += qf.y;
            hacc[2 * c + 0] += fmaxf(fmaf(sf.x, 1.f / F2N, pf.x), 0.f);
            hacc[2 * c + 1] += fmaxf(fmaf(sf.y, 1.f / F2N, pf.y), 0.f);
        }
    }

    {
        float* ph = &sH[w * 256 + lane * 8];
        float* pq = &sQ[w * 256 + lane * 8];
        *reinterpret_cast<float4*>(ph)     = make_float4(hacc[0], hacc[1], hacc[2], hacc[3]);
        *reinterpret_cast<float4*>(ph + 4) = make_float4(hacc[4], hacc[5], hacc[6], hacc[7]);
        *reinterpret_cast<float4*>(pq)     = make_float4(qacc[0], qacc[1], qacc[2], qacc[3]);
        *reinterpret_cast<float4*>(pq + 4) = make_float4(qacc[4], qacc[5], qacc[6], qacc[7]);
    }
    __syncthreads();

    float hx = 0.f, hy = 0.f, qx = 0.f, qy = 0.f;
#pragma unroll
    for (int ww = 0; ww < 4; ww++) {
        float2 hv = *reinterpret_cast<const float2*>(&sH[ww * 256 + 2 * tid]);
        float2 qv = *reinterpret_cast<const float2*>(&sQ[ww * 256 + 2 * tid]);
        hx += hv.x; hy += hv.y;
        qx += qv.x; qy += qv.y;
    }
    float2 p0 = __half22float2(
        reinterpret_cast<const __half2*>(g_Ph)[(size_t)T0[b] * 128 + tid]);
    float h0x = fmaxf(fmaf(qx, 1.f / F1N, p0.x), 0.f);
    float h0y = fmaxf(fmaf(qy, 1.f / F1N, p0.y), 0.f);
    __half2* C2 = reinterpret_cast<__half2*>(g_combh);
    C2[(size_t)b * 256 + tid]       = __floats2half2_rn(h0x, h0y);
    C2[(size_t)b * 256 + 128 + tid] = __floats2half2_rn(hx * (1.f / F1N), hy * (1.f / F1N));
}

// ---------------- scores: 32 batch rows per block (unchanged) ----------------
__global__ __launch_bounds__(256)
void scores_k(float* __restrict__ out) {
    int b0 = blockIdx.x * 32;
    __shared__ __align__(16) float sE[32 * 257];
    int tid = threadIdx.x;
#pragma unroll
    for (int it = 0; it < 8; it++) {
        int i = tid + it * 256;
        int r = i >> 6, k4 = (i & 63) * 4;
        float4 v = *reinterpret_cast<const float4*>(&g_E[(size_t)(b0 + r) * 256 + k4]);
        float* p = &sE[r * 257 + k4];
        p[0] = v.x; p[1] = v.y; p[2] = v.z; p[3] = v.w;
    }
    __syncthreads();

    int col = tid & 63, rg = tid >> 6;
    float a[8];
#pragma unroll
    for (int i = 0; i < 8; i++) a[i] = 0.f;
#pragma unroll 4
    for (int k = 0; k < 256; k++) {
        float w = g_W3t[k * 64 + col];
        const float* pe = &sE[(rg * 8) * 257 + k];
#pragma unroll
        for (int i = 0; i < 8; i++) a[i] = fmaf(pe[i * 257], w, a[i]);
    }
#pragma unroll
    for (int i = 0; i < 8; i++)
        out[(size_t)(b0 + rg * 8 + i) * 64 + col] = a[i];
}

// ---------------- launch ----------------
extern "C" void kernel_launch(void* const* d_in, const int* in_sizes, int n_in,
                              void* d_out, int out_size) {
    const int*   T0  = (const int*)d_in[0];
    const int*   T1  = (const int*)d_in[1];
    const int*   T2  = (const int*)d_in[2];
    const float* emb = (const float*)d_in[3];
    const float* W1  = (const float*)d_in[4];
    const float* W2  = (const float*)d_in[5];
    const float* W3  = (const float*)d_in[6];
    float* out = (float*)d_out;
    (void)in_sizes; (void)n_in; (void)out_size;

    __half *Ph, *Qh, *B1h, *W2th, *combh;
    float* E;
    cudaGetSymbolAddress((void**)&Ph,    g_Ph);
    cudaGetSymbolAddress((void**)&Qh,    g_Qh);
    cudaGetSymbolAddress((void**)&B1h,   g_B1h);
    cudaGetSymbolAddress((void**)&W2th,  g_W2th);
    cudaGetSymbolAddress((void**)&combh, g_combh);
    cudaGetSymbolAddress((void**)&E,     g_E);

    cudaFuncSetAttribute((const void*)gemm_f16<false, 2, __half, true, 2, true>,
                         cudaFuncAttributeMaxDynamicSharedMemorySize, SMEM_PQ);
    cudaFuncSetAttribute((const void*)gemm_f16<true, 1, float, false, 3, false>,
                         cudaFuncAttributeMaxDynamicSharedMemorySize, SMEM_W2);

    // 1) weight prep only (emb conversion fused into PQ GEMM)
    prep_w<<<512, 256>>>(W1, W2, W3);

    // 2) [P|Q] = emb(fp32) @ B1h : [100000,256]x[256,512], fused convert, split out
    {
        dim3 grid(4, (NUM_NODES + 127) / 128);
        gemm_f16<false, 2, __half, true, 2, true><<<grid, 256, SMEM_PQ>>>(
            emb, B1h, Ph, Qh, NUM_NODES, 512, 256);
    }

    // 3) fused gathers/means/relu -> g_combh [4096, 512] fp16
    gather_fuse<<<BATCH, 128>>>(T0, T1, T2);

    // 4) E = relu(combh @ W2th): [4096,512]x[512,256] fp32 out (3-stage)
    {
        dim3 grid(2, BATCH / 64);
        gemm_f16<true, 1, float, false, 3, false><<<grid, 256, SMEM_W2>>>(
            combh, W2th, E, E, BATCH, 256, 512);
    }

    // 5) scores = E @ W3t (fp32 exact)
    scores_k<<<BATCH / 32, 256>>>(out);
}

// round 15
// speedup vs baseline: 1.2750x; 1.2750x over previous
#include <cuda_runtime.h>
#include <cuda_fp16.h>
#include <cstdint>
#include <cstddef>

#define NUM_NODES 100000
#define FEAT_DIM  256
#define BATCH     4096
#define F1N       25
#define F2N       10

// ---------------- static scratch ----------------
__device__ __half g_Ph[(size_t)NUM_NODES * 256];    // P = emb @ W1[:, :256].T
__device__ __half g_Qh[(size_t)NUM_NODES * 256];    // Q = emb @ W1[:, 256:].T
__device__ __half g_B1h[256 * 512];                 // [K=256][N=512] fp16
__device__ __half g_W2th[512 * 256];                // W2^T fp16 [k][n]
__device__ float  g_W3t[256 * 64];                  // W3^T fp32
__device__ __half g_combh[(size_t)BATCH * 512];     // [h0 | h1] fp16
__device__ float  g_E[(size_t)BATCH * 256];

// pack two fp32 -> fp16x2 (x -> lower, y -> upper; same rounding as __floats2half2_rn)
__device__ __forceinline__ uint32_t pack_h2(float x, float y) {
    uint32_t r;
    asm("cvt.rn.f16x2.f32 %0, %1, %2;" : "=r"(r) : "f"(y), "f"(x));
    return r;
}

// ---------------- weight prep only (emb conversion fused into PQ GEMM) ----
__global__ void prep_w(const float* __restrict__ W1,
                       const float* __restrict__ W2,
                       const float* __restrict__ W3) {
    int idx = blockIdx.x * blockDim.x + threadIdx.x;
    if (idx < 256 * 512) {   // B1h[k][n]
        int k = idx >> 9, n = idx & 511;
        float v = (n < 256) ? W1[n * 512 + k] : W1[(n - 256) * 512 + 256 + k];
        g_B1h[idx] = __float2half(v);
    }
    if (idx < 512 * 256) {   // W2th[k][n] = W2[n][k]
        int k = idx >> 8, n = idx & 255;
        g_W2th[idx] = __float2half(W2[n * 512 + k]);
    }
    if (idx < 256 * 64) {    // W3t[k][n] = W3[n][k]
        int k = idx >> 6, n = idx & 63;
        g_W3t[idx] = W3[n * 256 + k];
    }
}

// ---------------- fp16 tensor-core GEMM, BK=64, NSTAGE cp.async ----------------
// CONVA=true (MT=2, NSTAGE=2): A is fp32, read with fully-coalesced LDG.128
// (16 lanes = 256B contiguous), converted in-register, STS'd into the NEXT
// stage's fp16 A buffer in one block right after the opening sync.
// (R14's regression: 2-thread/row mapping -> 32 sectors per LDG; fixed here.)
// CONVA=false: fp16 A via cp.async (R13 path, unchanged).

__device__ __forceinline__ uint32_t smem_u32(const void* p) {
    return (uint32_t)__cvta_generic_to_shared(p);
}
__device__ __forceinline__ uint32_t a2_off(int row, int c) {
    return (uint32_t)(row * 128 + ((c ^ (row & 7)) * 16));
}
__device__ __forceinline__ uint32_t b2_off(int k, int c) {
    return (uint32_t)(k * 256 + (((c & 8) | ((c ^ k) & 7)) * 16));
}
__device__ __forceinline__ void cp16(uint32_t dst, const void* src, int pred16) {
    asm volatile("cp.async.cg.shared.global [%0], [%1], 16, %2;"
                 :: "r"(dst), "l"(src), "r"(pred16));
}
__device__ __forceinline__ void ldsm4(uint32_t& r0, uint32_t& r1, uint32_t& r2,
                                      uint32_t& r3, uint32_t a) {
    asm volatile("ldmatrix.sync.aligned.m8n8.x4.shared.b16 {%0,%1,%2,%3}, [%4];"
                 : "=r"(r0), "=r"(r1), "=r"(r2), "=r"(r3) : "r"(a));
}
__device__ __forceinline__ void ldsm4t(uint32_t& r0, uint32_t& r1, uint32_t& r2,
                                       uint32_t& r3, uint32_t a) {
    asm volatile("ldmatrix.sync.aligned.m8n8.x4.trans.shared.b16 {%0,%1,%2,%3}, [%4];"
                 : "=r"(r0), "=r"(r1), "=r"(r2), "=r"(r3) : "r"(a));
}
__device__ __forceinline__ void mma16816(float* d, const uint32_t* a, uint32_t b0,
                                         uint32_t b1) {
    asm volatile(
        "mma.sync.aligned.m16n8k16.row.col.f32.f16.f16.f32 "
        "{%0,%1,%2,%3}, {%4,%5,%6,%7}, {%8,%9}, {%0,%1,%2,%3};\n"
        : "+f"(d[0]), "+f"(d[1]), "+f"(d[2]), "+f"(d[3])
        : "r"(a[0]), "r"(a[1]), "r"(a[2]), "r"(a[3]), "r"(b0), "r"(b1));
}
__device__ __forceinline__ void store2o(float* C, size_t off, float x, float y) {
    *reinterpret_cast<float2*>(C + off) = make_float2(x, y);
}
__device__ __forceinline__ void store2o(__half* C, size_t off, float x, float y) {
    *reinterpret_cast<__half2*>(C + off) = __floats2half2_rn(x, y);
}

template <bool RELU, int MT, typename OutT, bool SPLIT, int NSTAGE, bool CONVA>
__global__ __launch_bounds__(256, 2)
void gemm_f16(const void* __restrict__ Ap, const __half* __restrict__ B,
              OutT* __restrict__ C0, OutT* __restrict__ C1, int M, int N, int K) {
    const int BM  = MT * 64;
    const int ASZ = BM * 128;
    const int BSZ = 64 * 256;
    const int STG = ASZ + BSZ;
    extern __shared__ __align__(16) char smem[];

    const __half* Ah = reinterpret_cast<const __half*>(Ap);
    const float*  Af = reinterpret_cast<const float*>(Ap);

    const int tid  = threadIdx.x;
    const int lane = tid & 31;
    const int wid  = tid >> 5;
    const int warpM = wid & 3;
    const int warpN = wid >> 2;
    const int wbase = warpM * MT * 16;
    const int j8 = lane & 7;
    const int g8 = lane >> 3;
    const int m0 = blockIdx.y * BM;
    const int n0 = blockIdx.x * 128;
    const uint32_t sbase = smem_u32(smem);

    float acc[MT][8][4];
#pragma unroll
    for (int mt = 0; mt < MT; mt++)
#pragma unroll
        for (int nt = 0; nt < 8; nt++)
#pragma unroll
            for (int c = 0; c < 4; c++) acc[mt][nt][c] = 0.f;

    const int NK = K / 64;

    // issue one 64-wide K stage of B (and A when !CONVA) via cp.async
    auto issue = [&](int s) {
        const uint32_t as = sbase + (s % NSTAGE) * STG;
        const uint32_t bs = as + ASZ;
        const int kb = s * 64;
        if (!CONVA) {
#pragma unroll
            for (int it = 0; it < MT * 2; it++) {
                int i = tid + it * 256;
                int row = i >> 3, c = i & 7;
                int gm = m0 + row;
                cp16(as + a2_off(row, c), Ah + (size_t)gm * K + kb + c * 8,
                     (gm < M) ? 16 : 0);
            }
        }
#pragma unroll
        for (int it = 0; it < 4; it++) {
            int i = tid + it * 256;
            int k = i >> 4, c = i & 15;
            cp16(bs + b2_off(k, c), B + (size_t)(kb + k) * N + n0 + c * 8, 16);
        }
        asm volatile("cp.async.commit_group;");
    };

    // CONVA: fp32 A tile of stage s -> fp16 smem buffer (s % 2).
    // Mapping: i = tid + t*256 -> row = i>>4 (0..127), c4 = i&15 (float4 within
    // the 64-col slice). 16 consecutive lanes cover 256B contiguous (coalesced).
    // Dest: fp16 chunk (c4>>1) of a2_off, +8B when c4 odd. 8 independent
    // iterations -> MLP 8.
    auto convert_stage = [&](int s) {
#pragma unroll
        for (int t = 0; t < 8; t++) {
            int i = tid + t * 256;
            int row = i >> 4, c4 = i & 15;
            int gm = m0 + row;
            float4 v = (gm < M)
                ? *reinterpret_cast<const float4*>(Af + (size_t)gm * K + s * 64 + c4 * 4)
                : make_float4(0.f, 0.f, 0.f, 0.f);
            uint2 o = make_uint2(pack_h2(v.x, v.y), pack_h2(v.z, v.w));
            *reinterpret_cast<uint2*>(
                smem + (s % 2) * STG + a2_off(row, c4 >> 1) + (c4 & 1) * 8) = o;
        }
    };

    if (NSTAGE == 2) {
        issue(0);
        if (CONVA) convert_stage(0);   // visible to all warps at iter-0 opening sync
    } else {
        issue(0);
        if (NK > 1) issue(1);
    }

    for (int i = 0; i < NK; i++) {
        if (NSTAGE == 2) {
            if (i + 1 < NK) {
                issue(i + 1);
                asm volatile("cp.async.wait_group 1;");
            } else {
                asm volatile("cp.async.wait_group 0;");
            }
            __syncthreads();
            // Buffer (i+1)%2's A region: last read in iter i-1; all warps are
            // past that (opening sync) -> safe to overwrite now. Trailing sync
            // publishes these stores before iter i+1 reads them.
            if (CONVA && i + 1 < NK) convert_stage(i + 1);
        } else {
            if (i == NK - 1) asm volatile("cp.async.wait_group 0;");
            else             asm volatile("cp.async.wait_group 1;");
            __syncthreads();
            if (i + 2 < NK) issue(i + 2);
        }

        const uint32_t as = sbase + (i % NSTAGE) * STG;
        const uint32_t bs = as + ASZ;
#pragma unroll
        for (int kk = 0; kk < 4; kk++) {
            uint32_t afr[MT][4];
#pragma unroll
            for (int mt = 0; mt < MT; mt++) {
                int row = wbase + mt * 16 + (g8 & 1) * 8 + j8;
                int ch  = kk * 2 + (g8 >> 1);
                ldsm4(afr[mt][0], afr[mt][1], afr[mt][2], afr[mt][3],
                      as + a2_off(row, ch));
            }
#pragma unroll
            for (int nt2 = 0; nt2 < 4; nt2++) {
                int kb = kk * 16 + (g8 & 1) * 8 + j8;
                int cb = ((warpN * 64 + nt2 * 16) >> 3) + (g8 >> 1);
                uint32_t b0, b1, b2, b3;
                ldsm4t(b0, b1, b2, b3, bs + b2_off(kb, cb));
#pragma unroll
                for (int mt = 0; mt < MT; mt++) {
                    mma16816(acc[mt][nt2 * 2 + 0], afr[mt], b0, b1);
                    mma16816(acc[mt][nt2 * 2 + 1], afr[mt], b2, b3);
                }
            }
        }
        __syncthreads();
    }

    const int gid = lane >> 2, lg = lane & 3;
    OutT* Cp = C0;
    int nbase = n0, Nout = N;
    if (SPLIT) {
        Nout = 256;
        if (n0 >= 256) { Cp = C1; nbase = n0 - 256; }
    }
#pragma unroll
    for (int mt = 0; mt < MT; mt++) {
        int r0 = m0 + wbase + mt * 16 + gid;
#pragma unroll
        for (int half = 0; half < 2; half++) {
            int gm = r0 + half * 8;
            if (gm >= M) continue;
#pragma unroll
            for (int nt = 0; nt < 8; nt++) {
                float x = acc[mt][nt][half * 2 + 0];
                float y = acc[mt][nt][half * 2 + 1];
                if (RELU) { x = fmaxf(x, 0.f); y = fmaxf(y, 0.f); }
                int col = nbase + warpN * 64 + nt * 8 + lg * 2;
                store2o(Cp, (size_t)gm * Nout + col, x, y);
            }
        }
    }
}

#define SMEM_PQ (2 * (128 * 128 + 64 * 256))   // 65536 B  (MT=2, 2-stage)
#define SMEM_W2 (3 * (64 * 128 + 64 * 256))    // 73728 B  (MT=1, 3-stage)

// ---------------- fused gather / mean / relu (R13, unchanged) ----------------
__global__ __launch_bounds__(128)
void gather_fuse(const int* __restrict__ T0, const int* __restrict__ T1,
                 const int* __restrict__ T2) {
    const int b = blockIdx.x;
    const int tid = threadIdx.x;
    const int lane = tid & 31;
    const int w = tid >> 5;

    __shared__ __align__(16) float sH[4 * 256];
    __shared__ __align__(16) float sQ[4 * 256];
    __shared__ int sT1[F1N];
    __shared__ int sT2[F1N * F2N];

    if (tid < F1N) sT1[tid] = T1[b * F1N + tid];
    for (int i = tid; i < F1N * F2N; i += 128) sT2[i] = T2[b * F1N * F2N + i];
    __syncthreads();

    const uint4* __restrict__ Pv = reinterpret_cast<const uint4*>(g_Ph);
    const uint4* __restrict__ Qv = reinterpret_cast<const uint4*>(g_Qh);

    float hacc[8], qacc[8];
#pragma unroll
    for (int c = 0; c < 8; c++) { hacc[c] = 0.f; qacc[c] = 0.f; }

    for (int i = w; i < F1N; i += 4) {
        const int n1 = sT1[i];
        uint4 pr = Pv[(size_t)n1 * 32 + lane];
        uint4 qr = Qv[(size_t)n1 * 32 + lane];
        uint4 aj[F2N];
#pragma unroll
        for (int j = 0; j < F2N; j++)
            aj[j] = Qv[(size_t)sT2[i * F2N + j] * 32 + lane];

        __half2 s[4];
#pragma unroll
        for (int c = 0; c < 4; c++) {
            __half2 t01 = __hadd2(((const __half2*)&aj[0])[c], ((const __half2*)&aj[1])[c]);
            __half2 t23 = __hadd2(((const __half2*)&aj[2])[c], ((const __half2*)&aj[3])[c]);
            __half2 t45 = __hadd2(((const __half2*)&aj[4])[c], ((const __half2*)&aj[5])[c]);
            __half2 t67 = __hadd2(((const __half2*)&aj[6])[c], ((const __half2*)&aj[7])[c]);
            __half2 t89 = __hadd2(((const __half2*)&aj[8])[c], ((const __half2*)&aj[9])[c]);
            __half2 q0 = __hadd2(t01, t23);
            __half2 q1 = __hadd2(t45, t67);
            s[c] = __hadd2(__hadd2(q0, q1), t89);
        }

#pragma unroll
        for (int c = 0; c < 4; c++) {
            float2 sf = __half22float2(s[c]);
            float2 pf = __half22float2(((const __half2*)&pr)[c]);
            float2 qf = __half22float2(((const __half2*)&qr)[c]);
            qacc[2 * c + 0] += qf.x;
            qacc[2 * c + 1] += qf.y;
            hacc[2 * c + 0] += fmaxf(fmaf(sf.x, 1.f / F2N, pf.x), 0.f);
            hacc[2 * c + 1] += fmaxf(fmaf(sf.y, 1.f / F2N, pf.y), 0.f);
        }
    }

    {
        float* ph = &sH[w * 256 + lane * 8];
        float* pq = &sQ[w * 256 + lane * 8];
        *reinterpret_cast<float4*>(ph)     = make_float4(hacc[0], hacc[1], hacc[2], hacc[3]);
        *reinterpret_cast<float4*>(ph + 4) = make_float4(hacc[4], hacc[5], hacc[6], hacc[7]);
        *reinterpret_cast<float4*>(pq)     = make_float4(qacc[0], qacc[1], qacc[2], qacc[3]);
        *reinterpret_cast<float4*>(pq + 4) = make_float4(qacc[4], qacc[5], qacc[6], qacc[7]);
    }
    __syncthreads();

    float hx = 0.f, hy = 0.f, qx = 0.f, qy = 0.f;
#pragma unroll
    for (int ww = 0; ww < 4; ww++) {
        float2 hv = *reinterpret_cast<const float2*>(&sH[ww * 256 + 2 * tid]);
        float2 qv = *reinterpret_cast<const float2*>(&sQ[ww * 256 + 2 * tid]);
        hx += hv.x; hy += hv.y;
        qx += qv.x; qy += qv.y;
    }
    float2 p0 = __half22float2(
        reinterpret_cast<const __half2*>(g_Ph)[(size_t)T0[b] * 128 + tid]);
    float h0x = fmaxf(fmaf(qx, 1.f / F1N, p0.x), 0.f);
    float h0y = fmaxf(fmaf(qy, 1.f / F1N, p0.y), 0.f);
    __half2* C2 = reinterpret_cast<__half2*>(g_combh);
    C2[(size_t)b * 256 + tid]       = __floats2half2_rn(h0x, h0y);
    C2[(size_t)b * 256 + 128 + tid] = __floats2half2_rn(hx * (1.f / F1N), hy * (1.f / F1N));
}

// ---------------- scores: 32 batch rows per block (unchanged) ----------------
__global__ __launch_bounds__(256)
void scores_k(float* __restrict__ out) {
    int b0 = blockIdx.x * 32;
    __shared__ __align__(16) float sE[32 * 257];
    int tid = threadIdx.x;
#pragma unroll
    for (int it = 0; it < 8; it++) {
        int i = tid + it * 256;
        int r = i >> 6, k4 = (i & 63) * 4;
        float4 v = *reinterpret_cast<const float4*>(&g_E[(size_t)(b0 + r) * 256 + k4]);
        float* p = &sE[r * 257 + k4];
        p[0] = v.x; p[1] = v.y; p[2] = v.z; p[3] = v.w;
    }
    __syncthreads();

    int col = tid & 63, rg = tid >> 6;
    float a[8];
#pragma unroll
    for (int i = 0; i < 8; i++) a[i] = 0.f;
#pragma unroll 4
    for (int k = 0; k < 256; k++) {
        float w = g_W3t[k * 64 + col];
        const float* pe = &sE[(rg * 8) * 257 + k];
#pragma unroll
        for (int i = 0; i < 8; i++) a[i] = fmaf(pe[i * 257], w, a[i]);
    }
#pragma unroll
    for (int i = 0; i < 8; i++)
        out[(size_t)(b0 + rg * 8 + i) * 64 + col] = a[i];
}

// ---------------- launch ----------------
extern "C" void kernel_launch(void* const* d_in, const int* in_sizes, int n_in,
                              void* d_out, int out_size) {
    const int*   T0  = (const int*)d_in[0];
    const int*   T1  = (const int*)d_in[1];
    const int*   T2  = (const int*)d_in[2];
    const float* emb = (const float*)d_in[3];
    const float* W1  = (const float*)d_in[4];
    const float* W2  = (const float*)d_in[5];
    const float* W3  = (const float*)d_in[6];
    float* out = (float*)d_out;
    (void)in_sizes; (void)n_in; (void)out_size;

    __half *Ph, *Qh, *B1h, *W2th, *combh;
    float* E;
    cudaGetSymbolAddress((void**)&Ph,    g_Ph);
    cudaGetSymbolAddress((void**)&Qh,    g_Qh);
    cudaGetSymbolAddress((void**)&B1h,   g_B1h);
    cudaGetSymbolAddress((void**)&W2th,  g_W2th);
    cudaGetSymbolAddress((void**)&combh, g_combh);
    cudaGetSymbolAddress((void**)&E,     g_E);

    cudaFuncSetAttribute((const void*)gemm_f16<false, 2, __half, true, 2, true>,
                         cudaFuncAttributeMaxDynamicSharedMemorySize, SMEM_PQ);
    cudaFuncSetAttribute((const void*)gemm_f16<true, 1, float, false, 3, false>,
                         cudaFuncAttributeMaxDynamicSharedMemorySize, SMEM_W2);

    // 1) weight prep only (emb conversion fused into PQ GEMM)
    prep_w<<<512, 256>>>(W1, W2, W3);

    // 2) [P|Q] = emb(fp32) @ B1h, fused coalesced convert, split fp16 outputs
    {
        dim3 grid(4, (NUM_NODES + 127) / 128);
        gemm_f16<false, 2, __half, true, 2, true><<<grid, 256, SMEM_PQ>>>(
            emb, B1h, Ph, Qh, NUM_NODES, 512, 256);
    }

    // 3) fused gathers/means/relu -> g_combh [4096, 512] fp16
    gather_fuse<<<BATCH, 128>>>(T0, T1, T2);

    // 4) E = relu(combh @ W2th): [4096,512]x[512,256] fp32 out (3-stage)
    {
        dim3 grid(2, BATCH / 64);
        gemm_f16<true, 1, float, false, 3, false><<<grid, 256, SMEM_W2>>>(
            combh, W2th, E, E, BATCH, 256, 512);
    }

    // 5) scores = E @ W3t (fp32 exact)
    scores_k<<<BATCH / 32, 256>>>(out);
}

// round 16
// speedup vs baseline: 1.3367x; 1.0484x over previous
#include <cuda_runtime.h>
#include <cuda_fp16.h>
#include <cstdint>
#include <cstddef>

#define NUM_NODES 100000
#define FEAT_DIM  256
#define BATCH     4096
#define F1N       25
#define F2N       10

// ---------------- static scratch ----------------
__device__ __half g_embh[(size_t)NUM_NODES * 256];  // fp16 copy of emb
__device__ __half g_Ph[(size_t)NUM_NODES * 256];    // P = emb @ W1[:, :256].T
__device__ __half g_Qh[(size_t)NUM_NODES * 256];    // Q = emb @ W1[:, 256:].T
__device__ __half g_B1h[256 * 512];                 // [K=256][N=512] fp16
__device__ __half g_W2th[512 * 256];                // W2^T fp16 [k][n]
__device__ float  g_W3t[256 * 64];                  // W3^T fp32
__device__ __half g_combh[(size_t)BATCH * 512];     // [h0 | h1] fp16
__device__ float  g_E[(size_t)BATCH * 256];

// ---------------- merged emb->fp16 conversion + weight prep (R13) ----------------
#define CONV_BLOCKS 25000
__global__ void prep_all(const float* __restrict__ emb,
                         const float* __restrict__ W1,
                         const float* __restrict__ W2,
                         const float* __restrict__ W3) {
    int b = blockIdx.x;
    if (b < CONV_BLOCKS) {
        size_t i = ((size_t)b * 256 + threadIdx.x) * 4;
        float4 v = *reinterpret_cast<const float4*>(emb + i);
        *reinterpret_cast<__half2*>(&g_embh[i])     = __floats2half2_rn(v.x, v.y);
        *reinterpret_cast<__half2*>(&g_embh[i + 2]) = __floats2half2_rn(v.z, v.w);
        return;
    }
    int idx = (b - CONV_BLOCKS) * 256 + threadIdx.x;
    if (idx < 256 * 512) {   // B1h[k][n]
        int k = idx >> 9, n = idx & 511;
        float v = (n < 256) ? W1[n * 512 + k] : W1[(n - 256) * 512 + 256 + k];
        g_B1h[idx] = __float2half(v);
    }
    if (idx < 512 * 256) {   // W2th[k][n] = W2[n][k]
        int k = idx >> 8, n = idx & 255;
        g_W2th[idx] = __float2half(W2[n * 512 + k]);
    }
    if (idx < 256 * 64) {    // W3t[k][n] = W3[n][k]
        int k = idx >> 6, n = idx & 63;
        g_W3t[idx] = W3[n * 256 + k];
    }
}

// ---------------- fp16 tensor-core GEMM, BK=64, NSTAGE cp.async (R13) ----------
__device__ __forceinline__ uint32_t smem_u32(const void* p) {
    return (uint32_t)__cvta_generic_to_shared(p);
}
__device__ __forceinline__ uint32_t a2_off(int row, int c) {
    return (uint32_t)(row * 128 + ((c ^ (row & 7)) * 16));
}
__device__ __forceinline__ uint32_t b2_off(int k, int c) {
    return (uint32_t)(k * 256 + (((c & 8) | ((c ^ k) & 7)) * 16));
}
__device__ __forceinline__ void cp16(uint32_t dst, const void* src, int pred16) {
    asm volatile("cp.async.cg.shared.global [%0], [%1], 16, %2;"
                 :: "r"(dst), "l"(src), "r"(pred16));
}
__device__ __forceinline__ void ldsm4(uint32_t& r0, uint32_t& r1, uint32_t& r2,
                                      uint32_t& r3, uint32_t a) {
    asm volatile("ldmatrix.sync.aligned.m8n8.x4.shared.b16 {%0,%1,%2,%3}, [%4];"
                 : "=r"(r0), "=r"(r1), "=r"(r2), "=r"(r3) : "r"(a));
}
__device__ __forceinline__ void ldsm4t(uint32_t& r0, uint32_t& r1, uint32_t& r2,
                                       uint32_t& r3, uint32_t a) {
    asm volatile("ldmatrix.sync.aligned.m8n8.x4.trans.shared.b16 {%0,%1,%2,%3}, [%4];"
                 : "=r"(r0), "=r"(r1), "=r"(r2), "=r"(r3) : "r"(a));
}
__device__ __forceinline__ void mma16816(float* d, const uint32_t* a, uint32_t b0,
                                         uint32_t b1) {
    asm volatile(
        "mma.sync.aligned.m16n8k16.row.col.f32.f16.f16.f32 "
        "{%0,%1,%2,%3}, {%4,%5,%6,%7}, {%8,%9}, {%0,%1,%2,%3};\n"
        : "+f"(d[0]), "+f"(d[1]), "+f"(d[2]), "+f"(d[3])
        : "r"(a[0]), "r"(a[1]), "r"(a[2]), "r"(a[3]), "r"(b0), "r"(b1));
}
__device__ __forceinline__ void store2o(float* C, size_t off, float x, float y) {
    *reinterpret_cast<float2*>(C + off) = make_float2(x, y);
}
__device__ __forceinline__ void store2o(__half* C, size_t off, float x, float y) {
    *reinterpret_cast<__half2*>(C + off) = __floats2half2_rn(x, y);
}

template <bool RELU, int MT, typename OutT, bool SPLIT, int NSTAGE>
__global__ __launch_bounds__(256, 2)
void gemm_f16(const __half* __restrict__ A, const __half* __restrict__ B,
              OutT* __restrict__ C0, OutT* __restrict__ C1, int M, int N, int K) {
    const int BM  = MT * 64;
    const int ASZ = BM * 128;
    const int BSZ = 64 * 256;
    const int STG = ASZ + BSZ;
    extern __shared__ __align__(16) char smem[];

    const int tid  = threadIdx.x;
    const int lane = tid & 31;
    const int wid  = tid >> 5;
    const int warpM = wid & 3;
    const int warpN = wid >> 2;
    const int wbase = warpM * MT * 16;
    const int j8 = lane & 7;
    const int g8 = lane >> 3;
    const int m0 = blockIdx.y * BM;
    const int n0 = blockIdx.x * 128;
    const uint32_t sbase = smem_u32(smem);

    float acc[MT][8][4];
#pragma unroll
    for (int mt = 0; mt < MT; mt++)
#pragma unroll
        for (int nt = 0; nt < 8; nt++)
#pragma unroll
            for (int c = 0; c < 4; c++) acc[mt][nt][c] = 0.f;

    const int NK = K / 64;

    auto issue = [&](int s) {
        const uint32_t as = sbase + (s % NSTAGE) * STG;
        const uint32_t bs = as + ASZ;
        const int kb = s * 64;
#pragma unroll
        for (int it = 0; it < MT * 2; it++) {
            int i = tid + it * 256;
            int row = i >> 3, c = i & 7;
            int gm = m0 + row;
            cp16(as + a2_off(row, c), A + (size_t)gm * K + kb + c * 8,
                 (gm < M) ? 16 : 0);
        }
#pragma unroll
        for (int it = 0; it < 4; it++) {
            int i = tid + it * 256;
            int k = i >> 4, c = i & 15;
            cp16(bs + b2_off(k, c), B + (size_t)(kb + k) * N + n0 + c * 8, 16);
        }
        asm volatile("cp.async.commit_group;");
    };

    if (NSTAGE == 2) {
        issue(0);
    } else {
        issue(0);
        if (NK > 1) issue(1);
    }

    for (int i = 0; i < NK; i++) {
        if (NSTAGE == 2) {
            if (i + 1 < NK) {
                issue(i + 1);
                asm volatile("cp.async.wait_group 1;");
            } else {
                asm volatile("cp.async.wait_group 0;");
            }
            __syncthreads();
        } else {
            if (i == NK - 1) asm volatile("cp.async.wait_group 0;");
            else             asm volatile("cp.async.wait_group 1;");
            __syncthreads();
            if (i + 2 < NK) issue(i + 2);
        }

        const uint32_t as = sbase + (i % NSTAGE) * STG;
        const uint32_t bs = as + ASZ;
#pragma unroll
        for (int kk = 0; kk < 4; kk++) {
            uint32_t afr[MT][4];
#pragma unroll
            for (int mt = 0; mt < MT; mt++) {
                int row = wbase + mt * 16 + (g8 & 1) * 8 + j8;
                int ch  = kk * 2 + (g8 >> 1);
                ldsm4(afr[mt][0], afr[mt][1], afr[mt][2], afr[mt][3],
                      as + a2_off(row, ch));
            }
#pragma unroll
            for (int nt2 = 0; nt2 < 4; nt2++) {
                int kb = kk * 16 + (g8 & 1) * 8 + j8;
                int cb = ((warpN * 64 + nt2 * 16) >> 3) + (g8 >> 1);
                uint32_t b0, b1, b2, b3;
                ldsm4t(b0, b1, b2, b3, bs + b2_off(kb, cb));
#pragma unroll
                for (int mt = 0; mt < MT; mt++) {
                    mma16816(acc[mt][nt2 * 2 + 0], afr[mt], b0, b1);
                    mma16816(acc[mt][nt2 * 2 + 1], afr[mt], b2, b3);
                }
            }
        }
        __syncthreads();
    }

    const int gid = lane >> 2, lg = lane & 3;
    OutT* Cp = C0;
    int nbase = n0, Nout = N;
    if (SPLIT) {
        Nout = 256;
        if (n0 >= 256) { Cp = C1; nbase = n0 - 256; }
    }
#pragma unroll
    for (int mt = 0; mt < MT; mt++) {
        int r0 = m0 + wbase + mt * 16 + gid;
#pragma unroll
        for (int half = 0; half < 2; half++) {
            int gm = r0 + half * 8;
            if (gm >= M) continue;
#pragma unroll
            for (int nt = 0; nt < 8; nt++) {
                float x = acc[mt][nt][half * 2 + 0];
                float y = acc[mt][nt][half * 2 + 1];
                if (RELU) { x = fmaxf(x, 0.f); y = fmaxf(y, 0.f); }
                int col = nbase + warpN * 64 + nt * 8 + lg * 2;
                store2o(Cp, (size_t)gm * Nout + col, x, y);
            }
        }
    }
}

#define SMEM_PQ (2 * (128 * 128 + 64 * 256))   // 65536 B  (MT=2, 2-stage)
#define SMEM_W2 (3 * (64 * 128 + 64 * 256))    // 73728 B  (MT=1, 3-stage)

// ---------------- fused gather / mean / relu — v3 + unroll 2 ----------------
// Single change vs R13: outer neighbor loop unrolled 2x -> up to 24 independent
// LDG.128 in flight per thread (MLP 12 -> 24), halving exposed latency again.
__global__ __launch_bounds__(128)
void gather_fuse(const int* __restrict__ T0, const int* __restrict__ T1,
                 const int* __restrict__ T2) {
    const int b = blockIdx.x;
    const int tid = threadIdx.x;
    const int lane = tid & 31;
    const int w = tid >> 5;

    __shared__ __align__(16) float sH[4 * 256];
    __shared__ __align__(16) float sQ[4 * 256];
    __shared__ int sT1[F1N];
    __shared__ int sT2[F1N * F2N];

    if (tid < F1N) sT1[tid] = T1[b * F1N + tid];
    for (int i = tid; i < F1N * F2N; i += 128) sT2[i] = T2[b * F1N * F2N + i];
    __syncthreads();

    const uint4* __restrict__ Pv = reinterpret_cast<const uint4*>(g_Ph);
    const uint4* __restrict__ Qv = reinterpret_cast<const uint4*>(g_Qh);

    float hacc[8], qacc[8];
#pragma unroll
    for (int c = 0; c < 8; c++) { hacc[c] = 0.f; qacc[c] = 0.f; }

#pragma unroll 2
    for (int i = w; i < F1N; i += 4) {
        const int n1 = sT1[i];
        uint4 pr = Pv[(size_t)n1 * 32 + lane];
        uint4 qr = Qv[(size_t)n1 * 32 + lane];
        uint4 aj[F2N];
#pragma unroll
        for (int j = 0; j < F2N; j++)
            aj[j] = Qv[(size_t)sT2[i * F2N + j] * 32 + lane];

        __half2 s[4];
#pragma unroll
        for (int c = 0; c < 4; c++) {
            __half2 t01 = __hadd2(((const __half2*)&aj[0])[c], ((const __half2*)&aj[1])[c]);
            __half2 t23 = __hadd2(((const __half2*)&aj[2])[c], ((const __half2*)&aj[3])[c]);
            __half2 t45 = __hadd2(((const __half2*)&aj[4])[c], ((const __half2*)&aj[5])[c]);
            __half2 t67 = __hadd2(((const __half2*)&aj[6])[c], ((const __half2*)&aj[7])[c]);
            __half2 t89 = __hadd2(((const __half2*)&aj[8])[c], ((const __half2*)&aj[9])[c]);
            __half2 q0 = __hadd2(t01, t23);
            __half2 q1 = __hadd2(t45, t67);
            s[c] = __hadd2(__hadd2(q0, q1), t89);
        }

#pragma unroll
        for (int c = 0; c < 4; c++) {
            float2 sf = __half22float2(s[c]);
            float2 pf = __half22float2(((const __half2*)&pr)[c]);
            float2 qf = __half22float2(((const __half2*)&qr)[c]);
            qacc[2 * c + 0] += qf.x;
            qacc[2 * c + 1] += qf.y;
            hacc[2 * c + 0] += fmaxf(fmaf(sf.x, 1.f / F2N, pf.x), 0.f);
            hacc[2 * c + 1] += fmaxf(fmaf(sf.y, 1.f / F2N, pf.y), 0.f);
        }
    }

    {
        float* ph = &sH[w * 256 + lane * 8];
        float* pq = &sQ[w * 256 + lane * 8];
        *reinterpret_cast<float4*>(ph)     = make_float4(hacc[0], hacc[1], hacc[2], hacc[3]);
        *reinterpret_cast<float4*>(ph + 4) = make_float4(hacc[4], hacc[5], hacc[6], hacc[7]);
        *reinterpret_cast<float4*>(pq)     = make_float4(qacc[0], qacc[1], qacc[2], qacc[3]);
        *reinterpret_cast<float4*>(pq + 4) = make_float4(qacc[4], qacc[5], qacc[6], qacc[7]);
    }
    __syncthreads();

    float hx = 0.f, hy = 0.f, qx = 0.f, qy = 0.f;
#pragma unroll
    for (int ww = 0; ww < 4; ww++) {
        float2 hv = *reinterpret_cast<const float2*>(&sH[ww * 256 + 2 * tid]);
        float2 qv = *reinterpret_cast<const float2*>(&sQ[ww * 256 + 2 * tid]);
        hx += hv.x; hy += hv.y;
        qx += qv.x; qy += qv.y;
    }
    float2 p0 = __half22float2(
        reinterpret_cast<const __half2*>(g_Ph)[(size_t)T0[b] * 128 + tid]);
    float h0x = fmaxf(fmaf(qx, 1.f / F1N, p0.x), 0.f);
    float h0y = fmaxf(fmaf(qy, 1.f / F1N, p0.y), 0.f);
    __half2* C2 = reinterpret_cast<__half2*>(g_combh);
    C2[(size_t)b * 256 + tid]       = __floats2half2_rn(h0x, h0y);
    C2[(size_t)b * 256 + 128 + tid] = __floats2half2_rn(hx * (1.f / F1N), hy * (1.f / F1N));
}

// ---------------- scores: 32 batch rows per block (unchanged) ----------------
__global__ __launch_bounds__(256)
void scores_k(float* __restrict__ out) {
    int b0 = blockIdx.x * 32;
    __shared__ __align__(16) float sE[32 * 257];
    int tid = threadIdx.x;
#pragma unroll
    for (int it = 0; it < 8; it++) {
        int i = tid + it * 256;
        int r = i >> 6, k4 = (i & 63) * 4;
        float4 v = *reinterpret_cast<const float4*>(&g_E[(size_t)(b0 + r) * 256 + k4]);
        float* p = &sE[r * 257 + k4];
        p[0] = v.x; p[1] = v.y; p[2] = v.z; p[3] = v.w;
    }
    __syncthreads();

    int col = tid & 63, rg = tid >> 6;
    float a[8];
#pragma unroll
    for (int i = 0; i < 8; i++) a[i] = 0.f;
#pragma unroll 4
    for (int k = 0; k < 256; k++) {
        float w = g_W3t[k * 64 + col];
        const float* pe = &sE[(rg * 8) * 257 + k];
#pragma unroll
        for (int i = 0; i < 8; i++) a[i] = fmaf(pe[i * 257], w, a[i]);
    }
#pragma unroll
    for (int i = 0; i < 8; i++)
        out[(size_t)(b0 + rg * 8 + i) * 64 + col] = a[i];
}

// ---------------- launch ----------------
extern "C" void kernel_launch(void* const* d_in, const int* in_sizes, int n_in,
                              void* d_out, int out_size) {
    const int*   T0  = (const int*)d_in[0];
    const int*   T1  = (const int*)d_in[1];
    const int*   T2  = (const int*)d_in[2];
    const float* emb = (const float*)d_in[3];
    const float* W1  = (const float*)d_in[4];
    const float* W2  = (const float*)d_in[5];
    const float* W3  = (const float*)d_in[6];
    float* out = (float*)d_out;
    (void)in_sizes; (void)n_in; (void)out_size;

    __half *embh, *Ph, *Qh, *B1h, *W2th, *combh;
    float* E;
    cudaGetSymbolAddress((void**)&embh,  g_embh);
    cudaGetSymbolAddress((void**)&Ph,    g_Ph);
    cudaGetSymbolAddress((void**)&Qh,    g_Qh);
    cudaGetSymbolAddress((void**)&B1h,   g_B1h);
    cudaGetSymbolAddress((void**)&W2th,  g_W2th);
    cudaGetSymbolAddress((void**)&combh, g_combh);
    cudaGetSymbolAddress((void**)&E,     g_E);

    cudaFuncSetAttribute((const void*)gemm_f16<false, 2, __half, true, 2>,
                         cudaFuncAttributeMaxDynamicSharedMemorySize, SMEM_PQ);
    cudaFuncSetAttribute((const void*)gemm_f16<true, 1, float, false, 3>,
                         cudaFuncAttributeMaxDynamicSharedMemorySize, SMEM_W2);

    // 1) merged conversion + weight prep
    prep_all<<<CONV_BLOCKS + 512, 256>>>(emb, W1, W2, W3);

    // 2) [P|Q] = embh @ B1h : [100000,256]x[256,512], split fp16 outputs (2-stage)
    {
        dim3 grid(4, (NUM_NODES + 127) / 128);
        gemm_f16<false, 2, __half, true, 2><<<grid, 256, SMEM_PQ>>>(
            embh, B1h, Ph, Qh, NUM_NODES, 512, 256);
    }

    // 3) fused gathers/means/relu -> g_combh [4096, 512] fp16
    gather_fuse<<<BATCH, 128>>>(T0, T1, T2);

    // 4) E = relu(combh @ W2th): [4096,512]x[512,256] fp32 out (3-stage)
    {
        dim3 grid(2, BATCH / 64);
        gemm_f16<true, 1, float, false, 3><<<grid, 256, SMEM_W2>>>(
            combh, W2th, E, E, BATCH, 256, 512);
    }

    // 5) scores = E @ W3t (fp32 exact)
    scores_k<<<BATCH / 32, 256>>>(out);
}

// round 17
// speedup vs baseline: 1.3764x; 1.0297x over previous
#include <cuda_runtime.h>
#include <cuda_fp16.h>
#include <cstdint>
#include <cstddef>

#define NUM_NODES 100000
#define FEAT_DIM  256
#define BATCH     4096
#define F1N       25
#define F2N       10

// ---------------- static scratch ----------------
__device__ __half g_embh[(size_t)NUM_NODES * 256];  // fp16 copy of emb
__device__ __half g_Ph[(size_t)NUM_NODES * 256];    // P = emb @ W1[:, :256].T
__device__ __half g_Qh[(size_t)NUM_NODES * 256];    // Q = emb @ W1[:, 256:].T
__device__ __half g_B1h[256 * 512];                 // [K=256][N=512] fp16
__device__ __half g_W2th[512 * 256];                // W2^T fp16 [k][n]
__device__ float  g_W3t[256 * 64];                  // W3^T fp32
__device__ __half g_combh[(size_t)BATCH * 512];     // [h0 | h1] fp16
__device__ float  g_E[(size_t)BATCH * 256];

// ---------------- merged emb->fp16 conversion + weight prep ----------------
#define CONV_BLOCKS 25000
__global__ void prep_all(const float* __restrict__ emb,
                         const float* __restrict__ W1,
                         const float* __restrict__ W2,
                         const float* __restrict__ W3) {
    int b = blockIdx.x;
    if (b < CONV_BLOCKS) {
        size_t i = ((size_t)b * 256 + threadIdx.x) * 4;
        float4 v = *reinterpret_cast<const float4*>(emb + i);
        *reinterpret_cast<__half2*>(&g_embh[i])     = __floats2half2_rn(v.x, v.y);
        *reinterpret_cast<__half2*>(&g_embh[i + 2]) = __floats2half2_rn(v.z, v.w);
        return;
    }
    int idx = (b - CONV_BLOCKS) * 256 + threadIdx.x;
    if (idx < 256 * 512) {   // B1h[k][n]
        int k = idx >> 9, n = idx & 511;
        float v = (n < 256) ? W1[n * 512 + k] : W1[(n - 256) * 512 + 256 + k];
        g_B1h[idx] = __float2half(v);
    }
    if (idx < 512 * 256) {   // W2th[k][n] = W2[n][k]
        int k = idx >> 8, n = idx & 255;
        g_W2th[idx] = __float2half(W2[n * 512 + k]);
    }
    if (idx < 256 * 64) {    // W3t[k][n] = W3[n][k]
        int k = idx >> 6, n = idx & 63;
        g_W3t[idx] = W3[n * 256 + k];
    }
}

// ---------------- fp16 tensor-core GEMM, BK=64, 3-stage single-sync ----------
// Schedule per iter: wait(stage i) -> sync -> issue(stage i+2) -> compute(i%3).
// The trailing barrier is removed: at iter i's opening sync every warp has
// finished iter i-1's reads of buffer (i-1)%3 == (i+2)%3, so overwriting it is
// race-free; per-thread wait_group + the NEXT opening sync gives cross-thread
// visibility of a stage before any warp reads it. Halves barrier count/iter.

__device__ __forceinline__ uint32_t smem_u32(const void* p) {
    return (uint32_t)__cvta_generic_to_shared(p);
}
__device__ __forceinline__ uint32_t a2_off(int row, int c) {
    return (uint32_t)(row * 128 + ((c ^ (row & 7)) * 16));
}
__device__ __forceinline__ uint32_t b2_off(int k, int c) {
    return (uint32_t)(k * 256 + (((c & 8) | ((c ^ k) & 7)) * 16));
}
__device__ __forceinline__ void cp16(uint32_t dst, const void* src, int pred16) {
    asm volatile("cp.async.cg.shared.global [%0], [%1], 16, %2;"
                 :: "r"(dst), "l"(src), "r"(pred16));
}
__device__ __forceinline__ void ldsm4(uint32_t& r0, uint32_t& r1, uint32_t& r2,
                                      uint32_t& r3, uint32_t a) {
    asm volatile("ldmatrix.sync.aligned.m8n8.x4.shared.b16 {%0,%1,%2,%3}, [%4];"
                 : "=r"(r0), "=r"(r1), "=r"(r2), "=r"(r3) : "r"(a));
}
__device__ __forceinline__ void ldsm4t(uint32_t& r0, uint32_t& r1, uint32_t& r2,
                                       uint32_t& r3, uint32_t a) {
    asm volatile("ldmatrix.sync.aligned.m8n8.x4.trans.shared.b16 {%0,%1,%2,%3}, [%4];"
                 : "=r"(r0), "=r"(r1), "=r"(r2), "=r"(r3) : "r"(a));
}
__device__ __forceinline__ void mma16816(float* d, const uint32_t* a, uint32_t b0,
                                         uint32_t b1) {
    asm volatile(
        "mma.sync.aligned.m16n8k16.row.col.f32.f16.f16.f32 "
        "{%0,%1,%2,%3}, {%4,%5,%6,%7}, {%8,%9}, {%0,%1,%2,%3};\n"
        : "+f"(d[0]), "+f"(d[1]), "+f"(d[2]), "+f"(d[3])
        : "r"(a[0]), "r"(a[1]), "r"(a[2]), "r"(a[3]), "r"(b0), "r"(b1));
}
__device__ __forceinline__ void store2o(float* C, size_t off, float x, float y) {
    *reinterpret_cast<float2*>(C + off) = make_float2(x, y);
}
__device__ __forceinline__ void store2o(__half* C, size_t off, float x, float y) {
    *reinterpret_cast<__half2*>(C + off) = __floats2half2_rn(x, y);
}

template <bool RELU, int MT, typename OutT, bool SPLIT>
__global__ __launch_bounds__(256, 2)
void gemm_f16(const __half* __restrict__ A, const __half* __restrict__ B,
              OutT* __restrict__ C0, OutT* __restrict__ C1, int M, int N, int K) {
    const int BM  = MT * 64;
    const int ASZ = BM * 128;
    const int BSZ = 64 * 256;
    const int STG = ASZ + BSZ;
    extern __shared__ __align__(16) char smem[];

    const int tid  = threadIdx.x;
    const int lane = tid & 31;
    const int wid  = tid >> 5;
    const int warpM = wid & 3;
    const int warpN = wid >> 2;
    const int wbase = warpM * MT * 16;
    const int j8 = lane & 7;
    const int g8 = lane >> 3;
    const int m0 = blockIdx.y * BM;
    const int n0 = blockIdx.x * 128;
    const uint32_t sbase = smem_u32(smem);

    float acc[MT][8][4];
#pragma unroll
    for (int mt = 0; mt < MT; mt++)
#pragma unroll
        for (int nt = 0; nt < 8; nt++)
#pragma unroll
            for (int c = 0; c < 4; c++) acc[mt][nt][c] = 0.f;

    const int NK = K / 64;

    auto issue = [&](int s) {
        const uint32_t as = sbase + (s % 3) * STG;
        const uint32_t bs = as + ASZ;
        const int kb = s * 64;
#pragma unroll
        for (int it = 0; it < MT * 2; it++) {
            int i = tid + it * 256;
            int row = i >> 3, c = i & 7;
            int gm = m0 + row;
            cp16(as + a2_off(row, c), A + (size_t)gm * K + kb + c * 8,
                 (gm < M) ? 16 : 0);
        }
#pragma unroll
        for (int it = 0; it < 4; it++) {
            int i = tid + it * 256;
            int k = i >> 4, c = i & 15;
            cp16(bs + b2_off(k, c), B + (size_t)(kb + k) * N + n0 + c * 8, 16);
        }
        asm volatile("cp.async.commit_group;");
    };

    issue(0);
    if (NK > 1) issue(1);

    for (int i = 0; i < NK; i++) {
        if (i + 1 < NK) asm volatile("cp.async.wait_group 1;");
        else            asm volatile("cp.async.wait_group 0;");
        __syncthreads();                 // single barrier per iteration
        if (i + 2 < NK) issue(i + 2);    // overwrites (i-1)%3: all reads done

        const uint32_t as = sbase + (i % 3) * STG;
        const uint32_t bs = as + ASZ;
#pragma unroll
        for (int kk = 0; kk < 4; kk++) {
            uint32_t afr[MT][4];
#pragma unroll
            for (int mt = 0; mt < MT; mt++) {
                int row = wbase + mt * 16 + (g8 & 1) * 8 + j8;
                int ch  = kk * 2 + (g8 >> 1);
                ldsm4(afr[mt][0], afr[mt][1], afr[mt][2], afr[mt][3],
                      as + a2_off(row, ch));
            }
#pragma unroll
            for (int nt2 = 0; nt2 < 4; nt2++) {
                int kb = kk * 16 + (g8 & 1) * 8 + j8;
                int cb = ((warpN * 64 + nt2 * 16) >> 3) + (g8 >> 1);
                uint32_t b0, b1, b2, b3;
                ldsm4t(b0, b1, b2, b3, bs + b2_off(kb, cb));
#pragma unroll
                for (int mt = 0; mt < MT; mt++) {
                    mma16816(acc[mt][nt2 * 2 + 0], afr[mt], b0, b1);
                    mma16816(acc[mt][nt2 * 2 + 1], afr[mt], b2, b3);
                }
            }
        }
        // no trailing __syncthreads (3-stage ring makes it redundant)
    }

    const int gid = lane >> 2, lg = lane & 3;
    OutT* Cp = C0;
    int nbase = n0, Nout = N;
    if (SPLIT) {
        Nout = 256;
        if (n0 >= 256) { Cp = C1; nbase = n0 - 256; }
    }
#pragma unroll
    for (int mt = 0; mt < MT; mt++) {
        int r0 = m0 + wbase + mt * 16 + gid;
#pragma unroll
        for (int half = 0; half < 2; half++) {
            int gm = r0 + half * 8;
            if (gm >= M) continue;
#pragma unroll
            for (int nt = 0; nt < 8; nt++) {
                float x = acc[mt][nt][half * 2 + 0];
                float y = acc[mt][nt][half * 2 + 1];
                if (RELU) { x = fmaxf(x, 0.f); y = fmaxf(y, 0.f); }
                int col = nbase + warpN * 64 + nt * 8 + lg * 2;
                store2o(Cp, (size_t)gm * Nout + col, x, y);
            }
        }
    }
}

#define SMEM_PQ (3 * (128 * 128 + 64 * 256))   // 98304 B  (MT=2)
#define SMEM_W2 (3 * (64 * 128 + 64 * 256))    // 73728 B  (MT=1)

// ---------------- fused gather / mean / relu (R16, unchanged) ----------------
__global__ __launch_bounds__(128)
void gather_fuse(const int* __restrict__ T0, const int* __restrict__ T1,
                 const int* __restrict__ T2) {
    const int b = blockIdx.x;
    const int tid = threadIdx.x;
    const int lane = tid & 31;
    const int w = tid >> 5;

    __shared__ __align__(16) float sH[4 * 256];
    __shared__ __align__(16) float sQ[4 * 256];
    __shared__ int sT1[F1N];
    __shared__ int sT2[F1N * F2N];

    if (tid < F1N) sT1[tid] = T1[b * F1N + tid];
    for (int i = tid; i < F1N * F2N; i += 128) sT2[i] = T2[b * F1N * F2N + i];
    __syncthreads();

    const uint4* __restrict__ Pv = reinterpret_cast<const uint4*>(g_Ph);
    const uint4* __restrict__ Qv = reinterpret_cast<const uint4*>(g_Qh);

    float hacc[8], qacc[8];
#pragma unroll
    for (int c = 0; c < 8; c++) { hacc[c] = 0.f; qacc[c] = 0.f; }

#pragma unroll 2
    for (int i = w; i < F1N; i += 4) {
        const int n1 = sT1[i];
        uint4 pr = Pv[(size_t)n1 * 32 + lane];
        uint4 qr = Qv[(size_t)n1 * 32 + lane];
        uint4 aj[F2N];
#pragma unroll
        for (int j = 0; j < F2N; j++)
            aj[j] = Qv[(size_t)sT2[i * F2N + j] * 32 + lane];

        __half2 s[4];
#pragma unroll
        for (int c = 0; c < 4; c++) {
            __half2 t01 = __hadd2(((const __half2*)&aj[0])[c], ((const __half2*)&aj[1])[c]);
            __half2 t23 = __hadd2(((const __half2*)&aj[2])[c], ((const __half2*)&aj[3])[c]);
            __half2 t45 = __hadd2(((const __half2*)&aj[4])[c], ((const __half2*)&aj[5])[c]);
            __half2 t67 = __hadd2(((const __half2*)&aj[6])[c], ((const __half2*)&aj[7])[c]);
            __half2 t89 = __hadd2(((const __half2*)&aj[8])[c], ((const __half2*)&aj[9])[c]);
            __half2 q0 = __hadd2(t01, t23);
            __half2 q1 = __hadd2(t45, t67);
            s[c] = __hadd2(__hadd2(q0, q1), t89);
        }

#pragma unroll
        for (int c = 0; c < 4; c++) {
            float2 sf = __half22float2(s[c]);
            float2 pf = __half22float2(((const __half2*)&pr)[c]);
            float2 qf = __half22float2(((const __half2*)&qr)[c]);
            qacc[2 * c + 0] += qf.x;
            qacc[2 * c + 1] += qf.y;
            hacc[2 * c + 0] += fmaxf(fmaf(sf.x, 1.f / F2N, pf.x), 0.f);
            hacc[2 * c + 1] += fmaxf(fmaf(sf.y, 1.f / F2N, pf.y), 0.f);
        }
    }

    {
        float* ph = &sH[w * 256 + lane * 8];
        float* pq = &sQ[w * 256 + lane * 8];
        *reinterpret_cast<float4*>(ph)     = make_float4(hacc[0], hacc[1], hacc[2], hacc[3]);
        *reinterpret_cast<float4*>(ph + 4) = make_float4(hacc[4], hacc[5], hacc[6], hacc[7]);
        *reinterpret_cast<float4*>(pq)     = make_float4(qacc[0], qacc[1], qacc[2], qacc[3]);
        *reinterpret_cast<float4*>(pq + 4) = make_float4(qacc[4], qacc[5], qacc[6], qacc[7]);
    }
    __syncthreads();

    float hx = 0.f, hy = 0.f, qx = 0.f, qy = 0.f;
#pragma unroll
    for (int ww = 0; ww < 4; ww++) {
        float2 hv = *reinterpret_cast<const float2*>(&sH[ww * 256 + 2 * tid]);
        float2 qv = *reinterpret_cast<const float2*>(&sQ[ww * 256 + 2 * tid]);
        hx += hv.x; hy += hv.y;
        qx += qv.x; qy += qv.y;
    }
    float2 p0 = __half22float2(
        reinterpret_cast<const __half2*>(g_Ph)[(size_t)T0[b] * 128 + tid]);
    float h0x = fmaxf(fmaf(qx, 1.f / F1N, p0.x), 0.f);
    float h0y = fmaxf(fmaf(qy, 1.f / F1N, p0.y), 0.f);
    __half2* C2 = reinterpret_cast<__half2*>(g_combh);
    C2[(size_t)b * 256 + tid]       = __floats2half2_rn(h0x, h0y);
    C2[(size_t)b * 256 + 128 + tid] = __floats2half2_rn(hx * (1.f / F1N), hy * (1.f / F1N));
}

// ---------------- scores: 32 batch rows per block (unchanged) ----------------
__global__ __launch_bounds__(256)
void scores_k(float* __restrict__ out) {
    int b0 = blockIdx.x * 32;
    __shared__ __align__(16) float sE[32 * 257];
    int tid = threadIdx.x;
#pragma unroll
    for (int it = 0; it < 8; it++) {
        int i = tid + it * 256;
        int r = i >> 6, k4 = (i & 63) * 4;
        float4 v = *reinterpret_cast<const float4*>(&g_E[(size_t)(b0 + r) * 256 + k4]);
        float* p = &sE[r * 257 + k4];
        p[0] = v.x; p[1] = v.y; p[2] = v.z; p[3] = v.w;
    }
    __syncthreads();

    int col = tid & 63, rg = tid >> 6;
    float a[8];
#pragma unroll
    for (int i = 0; i < 8; i++) a[i] = 0.f;
#pragma unroll 4
    for (int k = 0; k < 256; k++) {
        float w = g_W3t[k * 64 + col];
        const float* pe = &sE[(rg * 8) * 257 + k];
#pragma unroll
        for (int i = 0; i < 8; i++) a[i] = fmaf(pe[i * 257], w, a[i]);
    }
#pragma unroll
    for (int i = 0; i < 8; i++)
        out[(size_t)(b0 + rg * 8 + i) * 64 + col] = a[i];
}

// ---------------- launch ----------------
extern "C" void kernel_launch(void* const* d_in, const int* in_sizes, int n_in,
                              void* d_out, int out_size) {
    const int*   T0  = (const int*)d_in[0];
    const int*   T1  = (const int*)d_in[1];
    const int*   T2  = (const int*)d_in[2];
    const float* emb = (const float*)d_in[3];
    const float* W1  = (const float*)d_in[4];
    const float* W2  = (const float*)d_in[5];
    const float* W3  = (const float*)d_in[6];
    float* out = (float*)d_out;
    (void)in_sizes; (void)n_in; (void)out_size;

    __half *embh, *Ph, *Qh, *B1h, *W2th, *combh;
    float* E;
    cudaGetSymbolAddress((void**)&embh,  g_embh);
    cudaGetSymbolAddress((void**)&Ph,    g_Ph);
    cudaGetSymbolAddress((void**)&Qh,    g_Qh);
    cudaGetSymbolAddress((void**)&B1h,   g_B1h);
    cudaGetSymbolAddress((void**)&W2th,  g_W2th);
    cudaGetSymbolAddress((void**)&combh, g_combh);
    cudaGetSymbolAddress((void**)&E,     g_E);

    cudaFuncSetAttribute((const void*)gemm_f16<false, 2, __half, true>,
                         cudaFuncAttributeMaxDynamicSharedMemorySize, SMEM_PQ);
    cudaFuncSetAttribute((const void*)gemm_f16<true, 1, float, false>,
                         cudaFuncAttributeMaxDynamicSharedMemorySize, SMEM_W2);

    // 1) merged conversion + weight prep
    prep_all<<<CONV_BLOCKS + 512, 256>>>(emb, W1, W2, W3);

    // 2) [P|Q] = embh @ B1h : [100000,256]x[256,512], split fp16 outputs
    {
        dim3 grid(4, (NUM_NODES + 127) / 128);
        gemm_f16<false, 2, __half, true><<<grid, 256, SMEM_PQ>>>(
            embh, B1h, Ph, Qh, NUM_NODES, 512, 256);
    }

    // 3) fused gathers/means/relu -> g_combh [4096, 512] fp16
    gather_fuse<<<BATCH, 128>>>(T0, T1, T2);

    // 4) E = relu(combh @ W2th): [4096,512]x[512,256] fp32 out
    {
        dim3 grid(2, BATCH / 64);
        gemm_f16<true, 1, float, false><<<grid, 256, SMEM_W2>>>(
            combh, W2th, E, E, BATCH, 256, 512);
    }

    // 5) scores = E @ W3t (fp32 exact)
    scores_k<<<BATCH / 32, 256>>>(out);
}